// round 13
// baseline (speedup 1.0000x reference)
#include <cuda_runtime.h>
#include <cuda_fp16.h>

// Fixed problem shapes
#define N_NODES   2048
#define N_CHILD   4096
#define NNZ_PER   32768
#define NNZ_TOT   (2 * NNZ_PER)
#define G         4                 // samples per compute block
#define NTHREADS  512
#define NWARPS    (NTHREADS / 32)   // 16
#define NGROUPS   (N_NODES / 32)    // 64 row-groups (one warp each)
#define MAXPAD    96                // group max ~55; margin; mult of 4
#define PAD_ENTRIES (NGROUPS * 32 * MAXPAD)

#define SC_THREADS 256
#define SC_EPT     4                                  // entries per thread
#define SC_BLOCKS  (NNZ_TOT / (SC_THREADS * SC_EPT))  // 64

// ---------------- static device scratch -------------------------------------
// SELL-32, 4-packed: group g, lane l, entry j lives at
//   g*32*MAXPAD + (j>>2)*128 + l*4 + (j&3)
// Entry encoding: (col << 19) | fp16bits(exp(w)); (e >> 16) == col*8 is a
// ready-made byte offset into the half4 ell[] table.
// Slab is NOT bulk-zeroed; the fused finalize (last scatter block) zeros only
// the pad slots [fill_r, 4*lenb_g) k_main will read, and resets g_fill/g_z/
// g_done for the next graph replay (statics are zero-init on first run).
// +128 guard entries cover k_main's unconditional prefetch.
__device__ unsigned g_pad[PAD_ENTRIES + 128];
__device__ int      g_fill[N_NODES];       // zero-init; reset by finalize
__device__ int      g_grouplen[NGROUPS];   // uint4 iterations = ceil(maxfill/4)
__device__ float    g_z[N_NODES];          // zero-init; reset by finalize
__device__ float    g_logz[N_NODES];
__device__ unsigned g_done;                // scatter arrival counter

// ---------------- scatter + fused finalize ------------------------------------
// 64 blocks x 256 threads, 4 entries/thread via vector loads (4 independent
// atomic chains per thread -> 4x MLP on this latency-bound kernel). The last
// block to finish runs the finalize for all 2048 rows (threadfence/arrival-
// counter pattern), removing a separate launch.
__global__ void __launch_bounds__(SC_THREADS)
k_scatter(const int* __restrict__ r0, const int* __restrict__ c0,
          const float* __restrict__ d0,
          const int* __restrict__ r1, const int* __restrict__ c1,
          const float* __restrict__ d1) {
    const int tid = threadIdx.x;
    const int k4  = (blockIdx.x * SC_THREADS + tid) * SC_EPT;

    int4   rows4, cols4; float4 w4; int colofs;
    if (k4 < NNZ_PER) {
        rows4 = *(const int4*)(r0 + k4);
        cols4 = *(const int4*)(c0 + k4);
        w4    = *(const float4*)(d0 + k4);
        colofs = 0;
    } else {
        int j = k4 - NNZ_PER;
        rows4 = *(const int4*)(r1 + j);
        cols4 = *(const int4*)(c1 + j);
        w4    = *(const float4*)(d1 + j);
        colofs = N_CHILD;
    }

    #pragma unroll
    for (int q = 0; q < SC_EPT; ++q) {
        int   row = (q == 0) ? rows4.x : (q == 1) ? rows4.y
                  : (q == 2) ? rows4.z : rows4.w;
        int   col = ((q == 0) ? cols4.x : (q == 1) ? cols4.y
                  : (q == 2) ? cols4.z : cols4.w) + colofs;
        float w   = (q == 0) ? w4.x : (q == 1) ? w4.y
                  : (q == 2) ? w4.z : w4.w;
        float ew = __expf(w);
        atomicAdd(&g_z[row], ew);
        int j = atomicAdd(&g_fill[row], 1);
        if (j < MAXPAD) {
            int g = row >> 5, lane = row & 31;
            int pos = g * (32 * MAXPAD) + (j >> 2) * 128 + lane * 4 + (j & 3);
            unsigned h = (unsigned)__half_as_ushort(__float2half_rn(ew));
            g_pad[pos] = ((unsigned)col << 19) | h;
        }
    }

    // ---- arrival counter: last block runs finalize ----
    __shared__ int s_last;
    __threadfence();
    if (tid == 0) {
        unsigned old = atomicAdd(&g_done, 1u);
        s_last = (old == SC_BLOCKS - 1);
        if (s_last) g_done = 0u;   // reset for next replay
    }
    __syncthreads();
    if (!s_last) return;
    __threadfence();               // acquire all blocks' writes

    // finalize: 2048 rows, 8 per thread; warp of 32 consecutive tids maps to
    // one 32-row group each iteration (lane == row & 31 preserved).
    #pragma unroll
    for (int it = 0; it < N_NODES / SC_THREADS; ++it) {
        const int r = it * SC_THREADS + tid;
        g_logz[r] = __logf(g_z[r]);
        int f = min(g_fill[r], MAXPAD);
        g_fill[r] = 0;
        g_z[r] = 0.f;
        int m = f;
        #pragma unroll
        for (int o = 16; o; o >>= 1)
            m = max(m, __shfl_xor_sync(0xFFFFFFFFu, m, o));
        const int lenb = (m + 3) >> 2;
        const int g = r >> 5, lane = r & 31;
        if (lane == 0) g_grouplen[g] = lenb;
        const int base = g * (32 * MAXPAD) + lane * 4;
        for (int j = f; j < 4 * lenb; ++j)
            g_pad[base + (j >> 2) * 128 + (j & 3)] = 0u;
    }
}

// ---------------- main compute kernel ----------------------------------------
// One block = G=4 samples; exp(ll) as half4 in 64 KB smem -> 3 CTAs/SM,
// 48 warps/SM. One warp = one 32-row group per pass. Software-pipelined:
// next SELL uint4 prefetched UNCONDITIONALLY (guard tail keeps it in-bounds);
// all 4 random LDS.64 gathers issued before any FMA; (e>>16) is a
// premultiplied byte offset. fp32 register accumulation.
__global__ void __launch_bounds__(NTHREADS, 3)
k_main(const float* __restrict__ ll0, const float* __restrict__ ll1,
       float* __restrict__ out) {
    extern __shared__ uint2 ell[];   // [2 * N_CHILD] half4 entries
    const int tid = threadIdx.x;
    const long long s0 = (long long)blockIdx.x * G;
    const float* p0 = ll0 + s0 * N_CHILD;
    const float* p1 = ll1 + s0 * N_CHILD;

    for (int i = tid; i < N_CHILD; i += NTHREADS) {
        float a0 = __expf(p0[i]);
        float a1 = __expf(p0[i + N_CHILD]);
        float a2 = __expf(p0[i + 2 * N_CHILD]);
        float a3 = __expf(p0[i + 3 * N_CHILD]);
        __half2 h01 = __floats2half2_rn(a0, a1);
        __half2 h23 = __floats2half2_rn(a2, a3);
        ell[i] = make_uint2(*(unsigned*)&h01, *(unsigned*)&h23);

        float b0 = __expf(p1[i]);
        float b1 = __expf(p1[i + N_CHILD]);
        float b2 = __expf(p1[i + 2 * N_CHILD]);
        float b3 = __expf(p1[i + 3 * N_CHILD]);
        __half2 g01 = __floats2half2_rn(b0, b1);
        __half2 g23 = __floats2half2_rn(b2, b3);
        ell[N_CHILD + i] = make_uint2(*(unsigned*)&g01, *(unsigned*)&g23);
    }
    __syncthreads();

    const char* __restrict__ ellb = (const char*)ell;
    const int warp = tid >> 5, lane = tid & 31;
    #pragma unroll
    for (int pass = 0; pass < NGROUPS / NWARPS; ++pass) {   // 4 passes
        const int g    = warp + pass * NWARPS;
        const int lenb = g_grouplen[g];
        const uint4* __restrict__ p4 =
            (const uint4*)(g_pad + g * (32 * MAXPAD)) + lane;
        float4 acc = make_float4(0.f, 0.f, 0.f, 0.f);

        uint4 cur = __ldg(p4);   // lenb >= 1 always (Poisson(32) rows)

        #pragma unroll 2
        for (int jb = 0; jb < lenb; ++jb) {
            uint4 nxt = __ldg(&p4[(jb + 1) * 32]);   // unconditional; guarded slab

            uint2 hv0 = *(const uint2*)(ellb + (cur.x >> 16));
            uint2 hv1 = *(const uint2*)(ellb + (cur.y >> 16));
            uint2 hv2 = *(const uint2*)(ellb + (cur.z >> 16));
            uint2 hv3 = *(const uint2*)(ellb + (cur.w >> 16));
            float w0 = __half2float(__ushort_as_half((unsigned short)(cur.x & 0xFFFFu)));
            float w1 = __half2float(__ushort_as_half((unsigned short)(cur.y & 0xFFFFu)));
            float w2 = __half2float(__ushort_as_half((unsigned short)(cur.z & 0xFFFFu)));
            float w3 = __half2float(__ushort_as_half((unsigned short)(cur.w & 0xFFFFu)));

            float2 a01 = __half22float2(*(__half2*)&hv0.x);
            float2 a23 = __half22float2(*(__half2*)&hv0.y);
            acc.x = fmaf(a01.x, w0, acc.x);
            acc.y = fmaf(a01.y, w0, acc.y);
            acc.z = fmaf(a23.x, w0, acc.z);
            acc.w = fmaf(a23.y, w0, acc.w);

            float2 b01 = __half22float2(*(__half2*)&hv1.x);
            float2 b23 = __half22float2(*(__half2*)&hv1.y);
            acc.x = fmaf(b01.x, w1, acc.x);
            acc.y = fmaf(b01.y, w1, acc.y);
            acc.z = fmaf(b23.x, w1, acc.z);
            acc.w = fmaf(b23.y, w1, acc.w);

            float2 c01 = __half22float2(*(__half2*)&hv2.x);
            float2 c23 = __half22float2(*(__half2*)&hv2.y);
            acc.x = fmaf(c01.x, w2, acc.x);
            acc.y = fmaf(c01.y, w2, acc.y);
            acc.z = fmaf(c23.x, w2, acc.z);
            acc.w = fmaf(c23.y, w2, acc.w);

            float2 d01 = __half22float2(*(__half2*)&hv3.x);
            float2 d23 = __half22float2(*(__half2*)&hv3.y);
            acc.x = fmaf(d01.x, w3, acc.x);
            acc.y = fmaf(d01.y, w3, acc.y);
            acc.z = fmaf(d23.x, w3, acc.z);
            acc.w = fmaf(d23.y, w3, acc.w);

            cur = nxt;
        }

        const int r = g * 32 + lane;
        float lz = g_logz[r];
        float* o = out + s0 * N_NODES + r;
        o[0]           = __logf(acc.x) - lz;
        o[N_NODES]     = __logf(acc.y) - lz;
        o[2 * N_NODES] = __logf(acc.z) - lz;
        o[3 * N_NODES] = __logf(acc.w) - lz;
    }
}

// ---------------- launch ------------------------------------------------------
extern "C" void kernel_launch(void* const* d_in, const int* in_sizes, int n_in,
                              void* d_out, int out_size) {
    const float* ll0 = (const float*)d_in[0];
    const float* ll1 = (const float*)d_in[1];
    const float* w0d = (const float*)d_in[2];
    const float* w1d = (const float*)d_in[3];
    const int*   w0r = (const int*)d_in[4];
    const int*   w0c = (const int*)d_in[5];
    const int*   w1r = (const int*)d_in[6];
    const int*   w1c = (const int*)d_in[7];
    float* out = (float*)d_out;

    const int S = in_sizes[0] / N_CHILD;   // 4096
    const int nblocks = S / G;             // 1024

    const int smem_bytes = 2 * N_CHILD * (int)sizeof(uint2);  // 64 KB
    cudaFuncSetAttribute(k_main, cudaFuncAttributeMaxDynamicSharedMemorySize,
                         smem_bytes);

    k_scatter<<<SC_BLOCKS, SC_THREADS>>>(w0r, w0c, w0d, w1r, w1c, w1d);
    k_main<<<nblocks, NTHREADS, smem_bytes>>>(ll0, ll1, out);
}

// round 14
// speedup vs baseline: 1.0253x; 1.0253x over previous
#include <cuda_runtime.h>
#include <cuda_fp16.h>

// Fixed problem shapes
#define N_NODES   2048
#define N_CHILD   4096
#define NNZ_PER   32768
#define NNZ_TOT   (2 * NNZ_PER)
#define G         4                 // samples per compute block
#define NTHREADS  512
#define NWARPS    (NTHREADS / 32)   // 16
#define NGROUPS   (N_NODES / 32)    // 64 row-groups (one warp each)
#define MAXPAD    96                // group max ~55; margin; mult of 4
#define PAD_ENTRIES (NGROUPS * 32 * MAXPAD)

#define SC_NBLK   64                // blocks that also perform the scatter
#define SC_EPT    2                 // 512 threads x 2 entries = 1024/block
#define NBLOCKS   1024              // wave 1 = 444 blocks >= SC_NBLK (no deadlock)

// ---------------- static device scratch -------------------------------------
// SELL-32, 4-packed: group g, lane l, entry j at g*32*MAXPAD + (j>>2)*128 +
// l*4 + (j&3). Entry = (col<<19) | fp16bits(exp(w)); (e>>16) is a premultiplied
// byte offset into the half4 ell[] table. Slab never bulk-zeroed: finalize
// zeros exactly the pad slots [fill_r, 4*lenb_g). +128 guard entries cover the
// unconditional prefetch. All counters self-reset each launch (zero-init on
// first run).
__device__ unsigned g_pad[PAD_ENTRIES + 128];
__device__ int      g_fill[N_NODES];
__device__ int      g_grouplen[NGROUPS];
__device__ float    g_z[N_NODES];
__device__ float    g_logz[N_NODES];
__device__ unsigned g_sc_done;   // scatter-block arrivals
__device__ unsigned g_go;        // finalize complete flag
__device__ unsigned g_fin;       // whole-grid completion counter

// ---------------- single fused kernel ----------------------------------------
__global__ void __launch_bounds__(NTHREADS, 3)
k_main(const float* __restrict__ ll0, const float* __restrict__ ll1,
       float* __restrict__ out,
       const int* __restrict__ r0, const int* __restrict__ c0,
       const float* __restrict__ d0,
       const int* __restrict__ r1, const int* __restrict__ c1,
       const float* __restrict__ d1) {
    extern __shared__ uint2 ell[];   // [2 * N_CHILD] half4 entries
    const int tid  = threadIdx.x;
    const int warp = tid >> 5, lane = tid & 31;

    // ---- phase A: blocks 0..63 scatter the sparse weights -------------------
    if (blockIdx.x < SC_NBLK) {
        int base = (blockIdx.x * NTHREADS + tid) * SC_EPT;
        const int *rr, *cc; const float* dd; int cofs, idx;
        if (base < NNZ_PER) { rr = r0; cc = c0; dd = d0; cofs = 0;      idx = base; }
        else                { rr = r1; cc = c1; dd = d1; cofs = N_CHILD; idx = base - NNZ_PER; }
        int2   rows = *(const int2*)(rr + idx);
        int2   cols = *(const int2*)(cc + idx);
        float2 ws   = *(const float2*)(dd + idx);
        #pragma unroll
        for (int q = 0; q < SC_EPT; ++q) {
            int   row = (q == 0) ? rows.x : rows.y;
            int   col = ((q == 0) ? cols.x : cols.y) + cofs;
            float ew  = __expf((q == 0) ? ws.x : ws.y);
            atomicAdd(&g_z[row], ew);
            int j = atomicAdd(&g_fill[row], 1);
            if (j < MAXPAD) {
                int gg = row >> 5, ll = row & 31;
                int pos = gg * (32 * MAXPAD) + (j >> 2) * 128 + ll * 4 + (j & 3);
                unsigned h = (unsigned)__half_as_ushort(__float2half_rn(ew));
                g_pad[pos] = ((unsigned)col << 19) | h;
            }
        }
        __threadfence();
        __shared__ int s_last;
        if (tid == 0) {
            unsigned old = atomicAdd(&g_sc_done, 1u);
            s_last = (old == SC_NBLK - 1);
        }
        __syncthreads();
        if (s_last) {
            __threadfence();   // acquire all scatter blocks' writes
            // finalize: 2048 rows, 4/thread; lane == r & 31 preserved
            #pragma unroll
            for (int it = 0; it < N_NODES / NTHREADS; ++it) {
                const int r = it * NTHREADS + tid;
                g_logz[r] = __logf(g_z[r]);
                int f = min(g_fill[r], MAXPAD);
                g_fill[r] = 0;
                g_z[r] = 0.f;
                int m = f;
                #pragma unroll
                for (int o = 16; o; o >>= 1)
                    m = max(m, __shfl_xor_sync(0xFFFFFFFFu, m, o));
                const int lenb = (m + 3) >> 2;
                const int gg = r >> 5, ll = r & 31;
                if (ll == 0) g_grouplen[gg] = lenb;
                const int bofs = gg * (32 * MAXPAD) + ll * 4;
                for (int j = f; j < 4 * lenb; ++j)
                    g_pad[bofs + (j >> 2) * 128 + (j & 3)] = 0u;
            }
            __syncthreads();
            if (tid == 0) {
                g_sc_done = 0u;          // reset for next replay
                __threadfence();         // publish finalize writes
                atomicExch(&g_go, 1u);   // release
            }
        }
    }

    // ---- phase B: every block fills its exp(ll) tile (independent of A) -----
    const long long s0 = (long long)blockIdx.x * G;
    const float* p0 = ll0 + s0 * N_CHILD;
    const float* p1 = ll1 + s0 * N_CHILD;
    for (int i = tid; i < N_CHILD; i += NTHREADS) {
        float a0 = __expf(p0[i]);
        float a1 = __expf(p0[i + N_CHILD]);
        float a2 = __expf(p0[i + 2 * N_CHILD]);
        float a3 = __expf(p0[i + 3 * N_CHILD]);
        __half2 h01 = __floats2half2_rn(a0, a1);
        __half2 h23 = __floats2half2_rn(a2, a3);
        ell[i] = make_uint2(*(unsigned*)&h01, *(unsigned*)&h23);

        float b0 = __expf(p1[i]);
        float b1 = __expf(p1[i + N_CHILD]);
        float b2 = __expf(p1[i + 2 * N_CHILD]);
        float b3 = __expf(p1[i + 3 * N_CHILD]);
        __half2 g01 = __floats2half2_rn(b0, b1);
        __half2 g23 = __floats2half2_rn(b2, b3);
        ell[N_CHILD + i] = make_uint2(*(unsigned*)&g01, *(unsigned*)&g23);
    }
    __syncthreads();

    // ---- wait for scatter+finalize (wave 1 contains all scatter blocks) -----
    if (tid == 0) {
        while (atomicAdd(&g_go, 0u) == 0u) __nanosleep(64);
        __threadfence();   // acquire g_pad/g_logz/g_grouplen
    }
    __syncthreads();

    // ---- phase C: gather loop (unchanged from best kernel) ------------------
    const char* __restrict__ ellb = (const char*)ell;
    #pragma unroll
    for (int pass = 0; pass < NGROUPS / NWARPS; ++pass) {   // 4 passes
        const int g    = warp + pass * NWARPS;
        const int lenb = g_grouplen[g];
        const uint4* __restrict__ p4 =
            (const uint4*)(g_pad + g * (32 * MAXPAD)) + lane;
        float4 acc = make_float4(0.f, 0.f, 0.f, 0.f);

        uint4 cur = __ldg(p4);   // lenb >= 1 always (Poisson(32) rows)

        #pragma unroll 2
        for (int jb = 0; jb < lenb; ++jb) {
            uint4 nxt = __ldg(&p4[(jb + 1) * 32]);   // unconditional; guarded slab

            uint2 hv0 = *(const uint2*)(ellb + (cur.x >> 16));
            uint2 hv1 = *(const uint2*)(ellb + (cur.y >> 16));
            uint2 hv2 = *(const uint2*)(ellb + (cur.z >> 16));
            uint2 hv3 = *(const uint2*)(ellb + (cur.w >> 16));
            float w0 = __half2float(__ushort_as_half((unsigned short)(cur.x & 0xFFFFu)));
            float w1 = __half2float(__ushort_as_half((unsigned short)(cur.y & 0xFFFFu)));
            float w2 = __half2float(__ushort_as_half((unsigned short)(cur.z & 0xFFFFu)));
            float w3 = __half2float(__ushort_as_half((unsigned short)(cur.w & 0xFFFFu)));

            float2 a01 = __half22float2(*(__half2*)&hv0.x);
            float2 a23 = __half22float2(*(__half2*)&hv0.y);
            acc.x = fmaf(a01.x, w0, acc.x);
            acc.y = fmaf(a01.y, w0, acc.y);
            acc.z = fmaf(a23.x, w0, acc.z);
            acc.w = fmaf(a23.y, w0, acc.w);

            float2 b01 = __half22float2(*(__half2*)&hv1.x);
            float2 b23 = __half22float2(*(__half2*)&hv1.y);
            acc.x = fmaf(b01.x, w1, acc.x);
            acc.y = fmaf(b01.y, w1, acc.y);
            acc.z = fmaf(b23.x, w1, acc.z);
            acc.w = fmaf(b23.y, w1, acc.w);

            float2 c01 = __half22float2(*(__half2*)&hv2.x);
            float2 c23 = __half22float2(*(__half2*)&hv2.y);
            acc.x = fmaf(c01.x, w2, acc.x);
            acc.y = fmaf(c01.y, w2, acc.y);
            acc.z = fmaf(c23.x, w2, acc.z);
            acc.w = fmaf(c23.y, w2, acc.w);

            float2 d01 = __half22float2(*(__half2*)&hv3.x);
            float2 d23 = __half22float2(*(__half2*)&hv3.y);
            acc.x = fmaf(d01.x, w3, acc.x);
            acc.y = fmaf(d01.y, w3, acc.y);
            acc.z = fmaf(d23.x, w3, acc.z);
            acc.w = fmaf(d23.y, w3, acc.w);

            cur = nxt;
        }

        const int r = g * 32 + lane;
        float lz = g_logz[r];
        float* o = out + s0 * N_NODES + r;
        o[0]           = __logf(acc.x) - lz;
        o[N_NODES]     = __logf(acc.y) - lz;
        o[2 * N_NODES] = __logf(acc.z) - lz;
        o[3 * N_NODES] = __logf(acc.w) - lz;
    }

    // ---- reset flags for next replay (last finishing block) -----------------
    __syncthreads();
    if (tid == 0) {
        unsigned old = atomicAdd(&g_fin, 1u);
        if (old == NBLOCKS - 1) {
            g_fin = 0u;
            atomicExch(&g_go, 0u);
        }
    }
}

// ---------------- launch ------------------------------------------------------
extern "C" void kernel_launch(void* const* d_in, const int* in_sizes, int n_in,
                              void* d_out, int out_size) {
    const float* ll0 = (const float*)d_in[0];
    const float* ll1 = (const float*)d_in[1];
    const float* w0d = (const float*)d_in[2];
    const float* w1d = (const float*)d_in[3];
    const int*   w0r = (const int*)d_in[4];
    const int*   w0c = (const int*)d_in[5];
    const int*   w1r = (const int*)d_in[6];
    const int*   w1c = (const int*)d_in[7];
    float* out = (float*)d_out;

    const int smem_bytes = 2 * N_CHILD * (int)sizeof(uint2);  // 64 KB
    cudaFuncSetAttribute(k_main, cudaFuncAttributeMaxDynamicSharedMemorySize,
                         smem_bytes);

    k_main<<<NBLOCKS, NTHREADS, smem_bytes>>>(ll0, ll1, out,
                                              w0r, w0c, w0d, w1r, w1c, w1d);
}

// round 15
// speedup vs baseline: 1.0834x; 1.0568x over previous
#include <cuda_runtime.h>
#include <cuda_fp16.h>

// Fixed problem shapes
#define N_NODES   2048
#define N_CHILD   4096
#define NNZ_PER   32768
#define NNZ_TOT   (2 * NNZ_PER)
#define G         4                 // samples per compute block
#define NTHREADS  512
#define NWARPS    (NTHREADS / 32)   // 16
#define NGROUPS   (N_NODES / 32)    // 64 row-groups (one warp each)
#define MAXPAD    96                // group max ~55; margin; mult of 4
#define PAD_ENTRIES (NGROUPS * 32 * MAXPAD)

#define SC_THREADS 256
#define SC_EPT     4                                  // entries per thread
#define SC_BLOCKS  (NNZ_TOT / (SC_THREADS * SC_EPT))  // 64

// ---------------- static device scratch -------------------------------------
// SELL-32, 4-packed: group g, lane l, entry j lives at
//   g*32*MAXPAD + (j>>2)*128 + l*4 + (j&3)
// Entry encoding: (col << 19) | fp16bits(exp(w)); (e >> 16) == col*8 is a
// ready-made byte offset into the half4 ell[] table.
// Slab is NOT bulk-zeroed; k_finalize zeros exactly the pad slots
// [fill_r, 4*lenb_g) that k_main will read. +128 guard entries allow the
// unconditional prefetch in k_main to read one uint4 row past the last group.
__device__ unsigned g_pad[PAD_ENTRIES + 128];
__device__ int      g_fill[N_NODES];
__device__ int      g_grouplen[NGROUPS];  // uint4 iterations = ceil(maxfill/4)
__device__ float    g_z[N_NODES];
__device__ float    g_logz[N_NODES];

// ---------------- prep kernels ----------------------------------------------
__global__ void k_zero() {
    int i = blockIdx.x * blockDim.x + threadIdx.x;
    if (i < N_NODES) { g_fill[i] = 0; g_z[i] = 0.f; }
}

// 64 blocks x 256 threads, 4 entries/thread via vector loads: four
// independent ATOMG chains per thread -> 4x MLP on this latency-bound kernel.
__global__ void __launch_bounds__(SC_THREADS)
k_scatter(const int* __restrict__ r0, const int* __restrict__ c0,
          const float* __restrict__ d0,
          const int* __restrict__ r1, const int* __restrict__ c1,
          const float* __restrict__ d1) {
    const int k4 = (blockIdx.x * SC_THREADS + threadIdx.x) * SC_EPT;

    int4 rows4, cols4; float4 w4; int colofs;
    if (k4 < NNZ_PER) {
        rows4 = *(const int4*)(r0 + k4);
        cols4 = *(const int4*)(c0 + k4);
        w4    = *(const float4*)(d0 + k4);
        colofs = 0;
    } else {
        int j = k4 - NNZ_PER;
        rows4 = *(const int4*)(r1 + j);
        cols4 = *(const int4*)(c1 + j);
        w4    = *(const float4*)(d1 + j);
        colofs = N_CHILD;
    }

    #pragma unroll
    for (int q = 0; q < SC_EPT; ++q) {
        int   row = (q == 0) ? rows4.x : (q == 1) ? rows4.y
                  : (q == 2) ? rows4.z : rows4.w;
        int   col = ((q == 0) ? cols4.x : (q == 1) ? cols4.y
                  : (q == 2) ? cols4.z : cols4.w) + colofs;
        float w   = (q == 0) ? w4.x : (q == 1) ? w4.y
                  : (q == 2) ? w4.z : w4.w;
        float ew = __expf(w);
        atomicAdd(&g_z[row], ew);
        int j = atomicAdd(&g_fill[row], 1);
        if (j < MAXPAD) {
            int g = row >> 5, lane = row & 31;
            int pos = g * (32 * MAXPAD) + (j >> 2) * 128 + lane * 4 + (j & 3);
            unsigned h = (unsigned)__half_as_ushort(__float2half_rn(ew));
            g_pad[pos] = ((unsigned)col << 19) | h;
        }
    }
}

// logz per row, per-group length, and zero ONLY the pad slots k_main reads.
__global__ void k_finalize() {
    int r = blockIdx.x * blockDim.x + threadIdx.x;
    if (r >= N_NODES) return;
    g_logz[r] = __logf(g_z[r]);
    int f = min(g_fill[r], MAXPAD);
    int m = f;
    #pragma unroll
    for (int o = 16; o; o >>= 1)
        m = max(m, __shfl_xor_sync(0xFFFFFFFFu, m, o));
    const int lenb = (m + 3) >> 2;
    const int g = r >> 5, lane = r & 31;
    if (lane == 0) g_grouplen[g] = lenb;
    const int base = g * (32 * MAXPAD) + lane * 4;
    for (int j = f; j < 4 * lenb; ++j)
        g_pad[base + (j >> 2) * 128 + (j & 3)] = 0u;
}

// ---------------- main compute kernel ----------------------------------------
// One block = G=4 samples; exp(ll) as half4 in 64 KB smem -> 3 CTAs/SM,
// 48 warps/SM. One warp = one 32-row group per pass. Software-pipelined:
// next SELL uint4 prefetched UNCONDITIONALLY (guard tail keeps it in-bounds;
// last value never consumed); all 4 random LDS.64 gathers issued before any
// FMA; (e>>16) is a premultiplied byte offset. fp32 register accumulation.
__global__ void __launch_bounds__(NTHREADS, 3)
k_main(const float* __restrict__ ll0, const float* __restrict__ ll1,
       float* __restrict__ out) {
    extern __shared__ uint2 ell[];   // [2 * N_CHILD] half4 entries
    const int tid = threadIdx.x;
    const long long s0 = (long long)blockIdx.x * G;
    const float* p0 = ll0 + s0 * N_CHILD;
    const float* p1 = ll1 + s0 * N_CHILD;

    for (int i = tid; i < N_CHILD; i += NTHREADS) {
        float a0 = __expf(p0[i]);
        float a1 = __expf(p0[i + N_CHILD]);
        float a2 = __expf(p0[i + 2 * N_CHILD]);
        float a3 = __expf(p0[i + 3 * N_CHILD]);
        __half2 h01 = __floats2half2_rn(a0, a1);
        __half2 h23 = __floats2half2_rn(a2, a3);
        ell[i] = make_uint2(*(unsigned*)&h01, *(unsigned*)&h23);

        float b0 = __expf(p1[i]);
        float b1 = __expf(p1[i + N_CHILD]);
        float b2 = __expf(p1[i + 2 * N_CHILD]);
        float b3 = __expf(p1[i + 3 * N_CHILD]);
        __half2 g01 = __floats2half2_rn(b0, b1);
        __half2 g23 = __floats2half2_rn(b2, b3);
        ell[N_CHILD + i] = make_uint2(*(unsigned*)&g01, *(unsigned*)&g23);
    }
    __syncthreads();

    const char* __restrict__ ellb = (const char*)ell;
    const int warp = tid >> 5, lane = tid & 31;
    #pragma unroll
    for (int pass = 0; pass < NGROUPS / NWARPS; ++pass) {   // 4 passes
        const int g    = warp + pass * NWARPS;
        const int lenb = g_grouplen[g];
        const uint4* __restrict__ p4 =
            (const uint4*)(g_pad + g * (32 * MAXPAD)) + lane;
        float4 acc = make_float4(0.f, 0.f, 0.f, 0.f);

        uint4 cur = __ldg(p4);   // lenb >= 1 always (Poisson(32) rows)

        #pragma unroll 2
        for (int jb = 0; jb < lenb; ++jb) {
            uint4 nxt = __ldg(&p4[(jb + 1) * 32]);   // unconditional; guarded slab

            uint2 hv0 = *(const uint2*)(ellb + (cur.x >> 16));
            uint2 hv1 = *(const uint2*)(ellb + (cur.y >> 16));
            uint2 hv2 = *(const uint2*)(ellb + (cur.z >> 16));
            uint2 hv3 = *(const uint2*)(ellb + (cur.w >> 16));
            float w0 = __half2float(__ushort_as_half((unsigned short)(cur.x & 0xFFFFu)));
            float w1 = __half2float(__ushort_as_half((unsigned short)(cur.y & 0xFFFFu)));
            float w2 = __half2float(__ushort_as_half((unsigned short)(cur.z & 0xFFFFu)));
            float w3 = __half2float(__ushort_as_half((unsigned short)(cur.w & 0xFFFFu)));

            float2 a01 = __half22float2(*(__half2*)&hv0.x);
            float2 a23 = __half22float2(*(__half2*)&hv0.y);
            acc.x = fmaf(a01.x, w0, acc.x);
            acc.y = fmaf(a01.y, w0, acc.y);
            acc.z = fmaf(a23.x, w0, acc.z);
            acc.w = fmaf(a23.y, w0, acc.w);

            float2 b01 = __half22float2(*(__half2*)&hv1.x);
            float2 b23 = __half22float2(*(__half2*)&hv1.y);
            acc.x = fmaf(b01.x, w1, acc.x);
            acc.y = fmaf(b01.y, w1, acc.y);
            acc.z = fmaf(b23.x, w1, acc.z);
            acc.w = fmaf(b23.y, w1, acc.w);

            float2 c01 = __half22float2(*(__half2*)&hv2.x);
            float2 c23 = __half22float2(*(__half2*)&hv2.y);
            acc.x = fmaf(c01.x, w2, acc.x);
            acc.y = fmaf(c01.y, w2, acc.y);
            acc.z = fmaf(c23.x, w2, acc.z);
            acc.w = fmaf(c23.y, w2, acc.w);

            float2 d01 = __half22float2(*(__half2*)&hv3.x);
            float2 d23 = __half22float2(*(__half2*)&hv3.y);
            acc.x = fmaf(d01.x, w3, acc.x);
            acc.y = fmaf(d01.y, w3, acc.y);
            acc.z = fmaf(d23.x, w3, acc.z);
            acc.w = fmaf(d23.y, w3, acc.w);

            cur = nxt;
        }

        const int r = g * 32 + lane;
        float lz = g_logz[r];
        float* o = out + s0 * N_NODES + r;
        o[0]           = __logf(acc.x) - lz;
        o[N_NODES]     = __logf(acc.y) - lz;
        o[2 * N_NODES] = __logf(acc.z) - lz;
        o[3 * N_NODES] = __logf(acc.w) - lz;
    }
}

// ---------------- launch ------------------------------------------------------
extern "C" void kernel_launch(void* const* d_in, const int* in_sizes, int n_in,
                              void* d_out, int out_size) {
    const float* ll0 = (const float*)d_in[0];
    const float* ll1 = (const float*)d_in[1];
    const float* w0d = (const float*)d_in[2];
    const float* w1d = (const float*)d_in[3];
    const int*   w0r = (const int*)d_in[4];
    const int*   w0c = (const int*)d_in[5];
    const int*   w1r = (const int*)d_in[6];
    const int*   w1c = (const int*)d_in[7];
    float* out = (float*)d_out;

    const int S = in_sizes[0] / N_CHILD;   // 4096
    const int nblocks = S / G;             // 1024

    const int smem_bytes = 2 * N_CHILD * (int)sizeof(uint2);  // 64 KB
    cudaFuncSetAttribute(k_main, cudaFuncAttributeMaxDynamicSharedMemorySize,
                         smem_bytes);

    k_zero<<<(N_NODES + 255) / 256, 256>>>();
    k_scatter<<<SC_BLOCKS, SC_THREADS>>>(w0r, w0c, w0d, w1r, w1c, w1d);
    k_finalize<<<(N_NODES + 255) / 256, 256>>>();
    k_main<<<nblocks, NTHREADS, smem_bytes>>>(ll0, ll1, out);
}

// round 16
// speedup vs baseline: 1.1135x; 1.0278x over previous
#include <cuda_runtime.h>
#include <cuda_fp16.h>

// Fixed problem shapes
#define N_NODES   2048
#define N_CHILD   4096
#define NNZ_PER   32768
#define NNZ_TOT   (2 * NNZ_PER)
#define G         4                 // samples per compute block
#define NTHREADS  512
#define NWARPS    (NTHREADS / 32)   // 16
#define NGROUPS   (N_NODES / 32)    // 64 row-groups (one warp each)
#define MAXPAD    96                // group max ~55; margin; mult of 4
#define PAD_ENTRIES (NGROUPS * 32 * MAXPAD)

#define SC_THREADS 256
#define SC_EPT     4                                  // entries per thread
#define SC_BLOCKS  (NNZ_TOT / (SC_THREADS * SC_EPT))  // 64

// ---------------- static device scratch -------------------------------------
// SELL-32, 4-packed: group g, lane l, entry j lives at
//   g*32*MAXPAD + (j>>2)*128 + l*4 + (j&3)
// Entry encoding: (col << 19) | fp16bits(exp(w)); (e >> 16) == col*8 is a
// ready-made byte offset into the half4 ell[] table.
// Slab is NOT bulk-zeroed; k_finalize zeros exactly the pad slots
// [fill_r, 4*lenb_g) that k_main will read. +128 guard entries allow the
// unconditional prefetch in k_main to read one uint4 row past the last group.
__device__ unsigned g_pad[PAD_ENTRIES + 128];
__device__ int      g_fill[N_NODES];
__device__ int      g_grouplen[NGROUPS];  // uint4 iterations = ceil(maxfill/4)
__device__ float    g_z[N_NODES];
__device__ float    g_logz[N_NODES];

// ---------------- prep kernels ----------------------------------------------
__global__ void k_zero() {
    int i = blockIdx.x * blockDim.x + threadIdx.x;
    if (i < N_NODES) { g_fill[i] = 0; g_z[i] = 0.f; }
}

// 64 blocks x 256 threads, 4 entries/thread via vector loads: four
// independent ATOMG chains per thread -> 4x MLP on this latency-bound kernel.
__global__ void __launch_bounds__(SC_THREADS)
k_scatter(const int* __restrict__ r0, const int* __restrict__ c0,
          const float* __restrict__ d0,
          const int* __restrict__ r1, const int* __restrict__ c1,
          const float* __restrict__ d1) {
    const int k4 = (blockIdx.x * SC_THREADS + threadIdx.x) * SC_EPT;

    int4 rows4, cols4; float4 w4; int colofs;
    if (k4 < NNZ_PER) {
        rows4 = *(const int4*)(r0 + k4);
        cols4 = *(const int4*)(c0 + k4);
        w4    = *(const float4*)(d0 + k4);
        colofs = 0;
    } else {
        int j = k4 - NNZ_PER;
        rows4 = *(const int4*)(r1 + j);
        cols4 = *(const int4*)(c1 + j);
        w4    = *(const float4*)(d1 + j);
        colofs = N_CHILD;
    }

    #pragma unroll
    for (int q = 0; q < SC_EPT; ++q) {
        int   row = (q == 0) ? rows4.x : (q == 1) ? rows4.y
                  : (q == 2) ? rows4.z : rows4.w;
        int   col = ((q == 0) ? cols4.x : (q == 1) ? cols4.y
                  : (q == 2) ? cols4.z : cols4.w) + colofs;
        float w   = (q == 0) ? w4.x : (q == 1) ? w4.y
                  : (q == 2) ? w4.z : w4.w;
        float ew = __expf(w);
        atomicAdd(&g_z[row], ew);
        int j = atomicAdd(&g_fill[row], 1);
        if (j < MAXPAD) {
            int g = row >> 5, lane = row & 31;
            int pos = g * (32 * MAXPAD) + (j >> 2) * 128 + lane * 4 + (j & 3);
            unsigned h = (unsigned)__half_as_ushort(__float2half_rn(ew));
            g_pad[pos] = ((unsigned)col << 19) | h;
        }
    }
}

// logz per row, per-group length, and zero ONLY the pad slots k_main reads.
__global__ void k_finalize() {
    int r = blockIdx.x * blockDim.x + threadIdx.x;
    if (r >= N_NODES) return;
    g_logz[r] = __logf(g_z[r]);
    int f = min(g_fill[r], MAXPAD);
    int m = f;
    #pragma unroll
    for (int o = 16; o; o >>= 1)
        m = max(m, __shfl_xor_sync(0xFFFFFFFFu, m, o));
    const int lenb = (m + 3) >> 2;
    const int g = r >> 5, lane = r & 31;
    if (lane == 0) g_grouplen[g] = lenb;
    const int base = g * (32 * MAXPAD) + lane * 4;
    for (int j = f; j < 4 * lenb; ++j)
        g_pad[base + (j >> 2) * 128 + (j & 3)] = 0u;
}

// ---------------- main compute kernel ----------------------------------------
// One block = G=4 samples; exp(ll) as half4 in 64 KB smem -> 3 CTAs/SM,
// 48 warps/SM. Fill phase vectorized: float2 coalesced loads, uint4 (STS.128)
// smem stores (2 columns per store). Gather loop: one warp = one 32-row group
// per pass; next SELL uint4 prefetched UNCONDITIONALLY (guard tail in-bounds);
// all 4 random LDS.64 gathers issued before any FMA; (e>>16) is a
// premultiplied byte offset. fp32 register accumulation.
__global__ void __launch_bounds__(NTHREADS, 3)
k_main(const float* __restrict__ ll0, const float* __restrict__ ll1,
       float* __restrict__ out) {
    extern __shared__ uint2 ell[];   // [2 * N_CHILD] half4 entries
    const int tid = threadIdx.x;
    const long long s0 = (long long)blockIdx.x * G;
    const float* p0 = ll0 + s0 * N_CHILD;
    const float* p1 = ll1 + s0 * N_CHILD;

    #pragma unroll
    for (int t = 0; t < N_CHILD / 2 / NTHREADS; ++t) {   // 4 iterations
        const int c = 2 * (t * NTHREADS + tid);

        // layer 0: 2 columns x 4 samples
        {
            float2 a0 = *(const float2*)(p0 + c);
            float2 a1 = *(const float2*)(p0 + N_CHILD + c);
            float2 a2 = *(const float2*)(p0 + 2 * N_CHILD + c);
            float2 a3 = *(const float2*)(p0 + 3 * N_CHILD + c);
            __half2 cx01 = __floats2half2_rn(__expf(a0.x), __expf(a1.x));
            __half2 cx23 = __floats2half2_rn(__expf(a2.x), __expf(a3.x));
            __half2 cy01 = __floats2half2_rn(__expf(a0.y), __expf(a1.y));
            __half2 cy23 = __floats2half2_rn(__expf(a2.y), __expf(a3.y));
            uint4 st = make_uint4(*(unsigned*)&cx01, *(unsigned*)&cx23,
                                  *(unsigned*)&cy01, *(unsigned*)&cy23);
            *(uint4*)&ell[c] = st;
        }
        // layer 1
        {
            float2 a0 = *(const float2*)(p1 + c);
            float2 a1 = *(const float2*)(p1 + N_CHILD + c);
            float2 a2 = *(const float2*)(p1 + 2 * N_CHILD + c);
            float2 a3 = *(const float2*)(p1 + 3 * N_CHILD + c);
            __half2 cx01 = __floats2half2_rn(__expf(a0.x), __expf(a1.x));
            __half2 cx23 = __floats2half2_rn(__expf(a2.x), __expf(a3.x));
            __half2 cy01 = __floats2half2_rn(__expf(a0.y), __expf(a1.y));
            __half2 cy23 = __floats2half2_rn(__expf(a2.y), __expf(a3.y));
            uint4 st = make_uint4(*(unsigned*)&cx01, *(unsigned*)&cx23,
                                  *(unsigned*)&cy01, *(unsigned*)&cy23);
            *(uint4*)&ell[N_CHILD + c] = st;
        }
    }
    __syncthreads();

    const char* __restrict__ ellb = (const char*)ell;
    const int warp = tid >> 5, lane = tid & 31;
    #pragma unroll
    for (int pass = 0; pass < NGROUPS / NWARPS; ++pass) {   // 4 passes
        const int g    = warp + pass * NWARPS;
        const int lenb = g_grouplen[g];
        const uint4* __restrict__ p4 =
            (const uint4*)(g_pad + g * (32 * MAXPAD)) + lane;
        float4 acc = make_float4(0.f, 0.f, 0.f, 0.f);

        uint4 cur = __ldg(p4);   // lenb >= 1 always (Poisson(32) rows)

        #pragma unroll 2
        for (int jb = 0; jb < lenb; ++jb) {
            uint4 nxt = __ldg(&p4[(jb + 1) * 32]);   // unconditional; guarded slab

            uint2 hv0 = *(const uint2*)(ellb + (cur.x >> 16));
            uint2 hv1 = *(const uint2*)(ellb + (cur.y >> 16));
            uint2 hv2 = *(const uint2*)(ellb + (cur.z >> 16));
            uint2 hv3 = *(const uint2*)(ellb + (cur.w >> 16));
            float w0 = __half2float(__ushort_as_half((unsigned short)(cur.x & 0xFFFFu)));
            float w1 = __half2float(__ushort_as_half((unsigned short)(cur.y & 0xFFFFu)));
            float w2 = __half2float(__ushort_as_half((unsigned short)(cur.z & 0xFFFFu)));
            float w3 = __half2float(__ushort_as_half((unsigned short)(cur.w & 0xFFFFu)));

            float2 a01 = __half22float2(*(__half2*)&hv0.x);
            float2 a23 = __half22float2(*(__half2*)&hv0.y);
            acc.x = fmaf(a01.x, w0, acc.x);
            acc.y = fmaf(a01.y, w0, acc.y);
            acc.z = fmaf(a23.x, w0, acc.z);
            acc.w = fmaf(a23.y, w0, acc.w);

            float2 b01 = __half22float2(*(__half2*)&hv1.x);
            float2 b23 = __half22float2(*(__half2*)&hv1.y);
            acc.x = fmaf(b01.x, w1, acc.x);
            acc.y = fmaf(b01.y, w1, acc.y);
            acc.z = fmaf(b23.x, w1, acc.z);
            acc.w = fmaf(b23.y, w1, acc.w);

            float2 c01 = __half22float2(*(__half2*)&hv2.x);
            float2 c23 = __half22float2(*(__half2*)&hv2.y);
            acc.x = fmaf(c01.x, w2, acc.x);
            acc.y = fmaf(c01.y, w2, acc.y);
            acc.z = fmaf(c23.x, w2, acc.z);
            acc.w = fmaf(c23.y, w2, acc.w);

            float2 d01 = __half22float2(*(__half2*)&hv3.x);
            float2 d23 = __half22float2(*(__half2*)&hv3.y);
            acc.x = fmaf(d01.x, w3, acc.x);
            acc.y = fmaf(d01.y, w3, acc.y);
            acc.z = fmaf(d23.x, w3, acc.z);
            acc.w = fmaf(d23.y, w3, acc.w);

            cur = nxt;
        }

        const int r = g * 32 + lane;
        float lz = g_logz[r];
        float* o = out + s0 * N_NODES + r;
        o[0]           = __logf(acc.x) - lz;
        o[N_NODES]     = __logf(acc.y) - lz;
        o[2 * N_NODES] = __logf(acc.z) - lz;
        o[3 * N_NODES] = __logf(acc.w) - lz;
    }
}

// ---------------- launch ------------------------------------------------------
extern "C" void kernel_launch(void* const* d_in, const int* in_sizes, int n_in,
                              void* d_out, int out_size) {
    const float* ll0 = (const float*)d_in[0];
    const float* ll1 = (const float*)d_in[1];
    const float* w0d = (const float*)d_in[2];
    const float* w1d = (const float*)d_in[3];
    const int*   w0r = (const int*)d_in[4];
    const int*   w0c = (const int*)d_in[5];
    const int*   w1r = (const int*)d_in[6];
    const int*   w1c = (const int*)d_in[7];
    float* out = (float*)d_out;

    const int S = in_sizes[0] / N_CHILD;   // 4096
    const int nblocks = S / G;             // 1024

    const int smem_bytes = 2 * N_CHILD * (int)sizeof(uint2);  // 64 KB
    cudaFuncSetAttribute(k_main, cudaFuncAttributeMaxDynamicSharedMemorySize,
                         smem_bytes);

    k_zero<<<(N_NODES + 255) / 256, 256>>>();
    k_scatter<<<SC_BLOCKS, SC_THREADS>>>(w0r, w0c, w0d, w1r, w1c, w1d);
    k_finalize<<<(N_NODES + 255) / 256, 256>>>();
    k_main<<<nblocks, NTHREADS, smem_bytes>>>(ll0, ll1, out);
}